// round 2
// baseline (speedup 1.0000x reference)
#include <cuda_runtime.h>
#include <cuda_bf16.h>

#define NN    50000
#define NE    400000
#define INC   128
#define HID   256
#define ED    32

// ---------------- scratch (static device buffers; no allocation) ----------------
__device__ float g_Xs [NN * HID];   // per-node src-side pre-projection
__device__ float g_Xd [NN * HID];   // per-node dst-side pre-projection
__device__ float g_agg[NN * HID];   // mean aggregate
__device__ float g_h  [NN * HID];   // node features (ping)
__device__ float g_h2 [NN * HID];   // node features (pong)
__device__ float g_deg[NN];         // degree, then 1/max(deg,1)

// ---------------- utility kernels ----------------
__global__ void zero_kernel(float* p, int n4) {
    int i = blockIdx.x * blockDim.x + threadIdx.x;
    if (i < n4) reinterpret_cast<float4*>(p)[i] = make_float4(0.f, 0.f, 0.f, 0.f);
}

__global__ void deg_kernel(const int* __restrict__ dst, float* deg, int E) {
    int e = blockIdx.x * blockDim.x + threadIdx.x;
    if (e < E) atomicAdd(&deg[dst[e]], 1.0f);
}

__global__ void invdeg_kernel(float* deg, int n) {
    int i = blockIdx.x * blockDim.x + threadIdx.x;
    if (i < n) deg[i] = 1.0f / fmaxf(deg[i], 1.0f);
}

// ---------------- tiled fp32 GEMM: C = act( A1@W1 [+ A2@W2] + bias ) ----------------
// A row-major [M,K], W row-major [K,N], C row-major [M,N]. N % 128 == 0, K % 8 == 0.
// rowscale2 (optional) scales rows of A2 (used for mean-normalizing agg on the fly).
#define BM 128
#define BN 128
#define BK 8
#define TM 8
#define TN 8

__global__ __launch_bounds__(256) void gemm_dual_kernel(
    const float* __restrict__ A1, const float* __restrict__ W1, int K1,
    const float* __restrict__ A2, const float* __restrict__ W2, int K2,
    const float* __restrict__ rowscale2,
    const float* __restrict__ bias, int relu,
    float* __restrict__ C, int M, int N)
{
    __shared__ float As[BK][BM];
    __shared__ float Bs[BK][BN];

    const int bm  = blockIdx.y * BM;
    const int bn  = blockIdx.x * BN;
    const int tid = threadIdx.x;
    const int tr  = tid / (BN / TN);   // 0..15
    const int tc  = tid % (BN / TN);   // 0..15

    float acc[TM][TN];
#pragma unroll
    for (int i = 0; i < TM; i++)
#pragma unroll
        for (int j = 0; j < TN; j++) acc[i][j] = 0.f;

    // loader mapping
    const int aRow = tid >> 1;            // 0..127
    const int aCol = (tid & 1) * 4;       // 0 or 4
    const int bRow = tid >> 5;            // 0..7
    const int bCol = (tid & 31) * 4;      // 0..124

    for (int pass = 0; pass < 2; ++pass) {
        const float* A = pass ? A2 : A1;
        const float* W = pass ? W2 : W1;
        const int    K = pass ? K2 : K1;
        if (A == nullptr) continue;

        float scale = 1.f;
        bool  use_scale = (pass == 1) && (rowscale2 != nullptr);
        if (use_scale) {
            int r = bm + aRow;
            scale = (r < M) ? rowscale2[r] : 0.f;
        }

        for (int k0 = 0; k0 < K; k0 += BK) {
            // A tile: 128x8
            {
                int r = bm + aRow;
                float4 av = make_float4(0.f, 0.f, 0.f, 0.f);
                if (r < M)
                    av = *reinterpret_cast<const float4*>(A + (long)r * K + k0 + aCol);
                if (use_scale) { av.x *= scale; av.y *= scale; av.z *= scale; av.w *= scale; }
                As[aCol + 0][aRow] = av.x;
                As[aCol + 1][aRow] = av.y;
                As[aCol + 2][aRow] = av.z;
                As[aCol + 3][aRow] = av.w;
            }
            // B tile: 8x128
            {
                float4 bv = *reinterpret_cast<const float4*>(W + (long)(k0 + bRow) * N + bn + bCol);
                *reinterpret_cast<float4*>(&Bs[bRow][bCol]) = bv;
            }
            __syncthreads();

#pragma unroll
            for (int k = 0; k < BK; ++k) {
                float4 a0 = *reinterpret_cast<const float4*>(&As[k][tr * TM]);
                float4 a1 = *reinterpret_cast<const float4*>(&As[k][tr * TM + 4]);
                float4 b0 = *reinterpret_cast<const float4*>(&Bs[k][tc * TN]);
                float4 b1 = *reinterpret_cast<const float4*>(&Bs[k][tc * TN + 4]);
                float a[TM] = {a0.x, a0.y, a0.z, a0.w, a1.x, a1.y, a1.z, a1.w};
                float b[TN] = {b0.x, b0.y, b0.z, b0.w, b1.x, b1.y, b1.z, b1.w};
#pragma unroll
                for (int i = 0; i < TM; i++)
#pragma unroll
                    for (int j = 0; j < TN; j++)
                        acc[i][j] = fmaf(a[i], b[j], acc[i][j]);
            }
            __syncthreads();
        }
    }

    // epilogue
#pragma unroll
    for (int i = 0; i < TM; i++) {
        int r = bm + tr * TM + i;
        if (r >= M) continue;
#pragma unroll
        for (int j = 0; j < TN; j += 4) {
            int c = bn + tc * TN + j;
            float4 v = make_float4(acc[i][j], acc[i][j + 1], acc[i][j + 2], acc[i][j + 3]);
            if (bias) {
                v.x += bias[c];     v.y += bias[c + 1];
                v.z += bias[c + 2]; v.w += bias[c + 3];
            }
            if (relu) {
                v.x = fmaxf(v.x, 0.f); v.y = fmaxf(v.y, 0.f);
                v.z = fmaxf(v.z, 0.f); v.w = fmaxf(v.w, 0.f);
            }
            *reinterpret_cast<float4*>(C + (long)r * N + c) = v;
        }
    }
}

// ---------------- fused edge message + scatter-sum ----------------
// m_e[j] = relu(b[j] + Xs[src][j] + Xd[dst][j] + sum_k attr[e][k]*We[k][j])
// atomicAdd into agg[dst][j].  We: [32,256] row-major (rows 2C..2C+31 of ew).
#define EPB 16   // edges per block (divides NE)

__global__ __launch_bounds__(256) void edge_kernel(
    const float* __restrict__ Xs, const float* __restrict__ Xd,
    const float* __restrict__ eattr,
    const float* __restrict__ We, const float* __restrict__ bias,
    const int* __restrict__ src, const int* __restrict__ dst,
    float* __restrict__ agg, int E)
{
    __shared__ float sW[ED * HID];    // 32 KB
    __shared__ float sB[HID];
    __shared__ float sE[EPB][ED];
    __shared__ int   sS[EPB], sD[EPB];

    const int tid = threadIdx.x;
    for (int i = tid; i < ED * HID; i += 256) sW[i] = We[i];
    sB[tid] = bias[tid];

    const int e0 = blockIdx.x * EPB;
    for (int i = tid; i < EPB * ED; i += 256) {
        int e = e0 + (i >> 5);
        sE[i >> 5][i & 31] = (e < E) ? eattr[(long)e * ED + (i & 31)] : 0.f;
    }
    if (tid < EPB) {
        int e = e0 + tid;
        if (e < E) { sS[tid] = src[e]; sD[tid] = dst[e]; }
    }
    __syncthreads();

    const int j = tid;  // output channel 0..255
#pragma unroll 1
    for (int ei = 0; ei < EPB; ++ei) {
        int e = e0 + ei;
        if (e >= E) break;
        int s = sS[ei], d = sD[ei];
        float acc = sB[j] + Xs[(long)s * HID + j] + Xd[(long)d * HID + j];
#pragma unroll
        for (int k = 0; k < ED; k++)
            acc = fmaf(sE[ei][k], sW[k * HID + j], acc);
        acc = fmaxf(acc, 0.f);
        atomicAdd(&agg[(long)d * HID + j], acc);
    }
}

// ---------------- head: out[n] = dot(relu_feats[n], w2) + b2 ----------------
__global__ void head_out_kernel(const float* __restrict__ T,
                                const float* __restrict__ w2,
                                const float* __restrict__ b2,
                                float* __restrict__ out, int n)
{
    int gw   = (blockIdx.x * blockDim.x + threadIdx.x) >> 5;
    int lane = threadIdx.x & 31;
    if (gw >= n) return;
    const float* t = T + (long)gw * HID;
    float acc = 0.f;
#pragma unroll
    for (int k = lane; k < HID; k += 32) acc = fmaf(t[k], w2[k], acc);
#pragma unroll
    for (int o = 16; o; o >>= 1) acc += __shfl_xor_sync(0xffffffffu, acc, o);
    if (lane == 0) out[gw] = acc + b2[0];
}

// ---------------- host orchestration ----------------
static float* sym_addr(const void* symbol) {
    void* p = nullptr;
    cudaGetSymbolAddress(&p, symbol);
    return (float*)p;
}

static void run_gemm(const float* A1, const float* W1, int K1,
                     const float* A2, const float* W2, int K2,
                     const float* rowscale2, const float* bias, int relu,
                     float* C, int M, int N, cudaStream_t s)
{
    dim3 grid(N / BN, (M + BM - 1) / BM);
    gemm_dual_kernel<<<grid, 256, 0, s>>>(A1, W1, K1, A2, W2, K2, rowscale2, bias, relu, C, M, N);
}

extern "C" void kernel_launch(void* const* d_in, const int* in_sizes, int n_in,
                              void* d_out, int out_size)
{
    cudaStream_t s = 0;
    const float* x     = (const float*)d_in[0];
    const int*   eidx  = (const int*)  d_in[1];
    const float* eattr = (const float*)d_in[2];
    const float* e0_w  = (const float*)d_in[3];
    const float* e0_b  = (const float*)d_in[4];
    const float* n0_w  = (const float*)d_in[5];
    const float* n0_b  = (const float*)d_in[6];
    const float* e_w   = (const float*)d_in[7];   // [2, 544, 256]
    const float* e_b   = (const float*)d_in[8];   // [2, 256]
    const float* n_w   = (const float*)d_in[9];   // [2, 512, 256]
    const float* n_b   = (const float*)d_in[10];  // [2, 256]
    const float* h1_w  = (const float*)d_in[11];
    const float* h1_b  = (const float*)d_in[12];
    const float* h2_w  = (const float*)d_in[13];
    const float* h2_b  = (const float*)d_in[14];

    const int* src = eidx;
    const int* dst = eidx + NE;

    float* Xs  = sym_addr(g_Xs);
    float* Xd  = sym_addr(g_Xd);
    float* agg = sym_addr(g_agg);
    float* h   = sym_addr(g_h);
    float* h2  = sym_addr(g_h2);
    float* deg = sym_addr(g_deg);

    const int feat4 = NN * HID / 4;
    const int zthr  = 256;

    // degrees -> inverse degrees (recomputed every launch: deterministic)
    zero_kernel<<<(NN / 4 + zthr - 1) / zthr, zthr, 0, s>>>(deg, NN / 4);
    deg_kernel<<<(NE + 255) / 256, 256, 0, s>>>(dst, deg, NE);
    invdeg_kernel<<<(NN + 255) / 256, 256, 0, s>>>(deg, NN);

    // ---------- layer 0 (C = 128) ----------
    {
        const float* Ws = e0_w;                 // rows 0..127
        const float* Wd = e0_w + (long)INC * HID;  // rows 128..255
        const float* We = e0_w + (long)2 * INC * HID; // rows 256..287
        run_gemm(x, Ws, INC, nullptr, nullptr, 0, nullptr, nullptr, 0, Xs, NN, HID, s);
        run_gemm(x, Wd, INC, nullptr, nullptr, 0, nullptr, nullptr, 0, Xd, NN, HID, s);
        zero_kernel<<<(feat4 + zthr - 1) / zthr, zthr, 0, s>>>(agg, feat4);
        edge_kernel<<<NE / EPB, 256, 0, s>>>(Xs, Xd, eattr, We, e0_b, src, dst, agg, NE);
        // node update: h = relu(x @ n0_w[:128] + (agg/deg) @ n0_w[128:384] + n0_b)
        run_gemm(x, n0_w, INC, agg, n0_w + (long)INC * HID, HID, deg, n0_b, 1, h, NN, HID, s);
    }

    // ---------- layers 1..2 (C = 256) ----------
    float* cur = h;
    float* nxt = h2;
    for (int L = 0; L < 2; ++L) {
        const float* ew = e_w + (long)L * (2 * HID + ED) * HID;
        const float* eb = e_b + (long)L * HID;
        const float* nw = n_w + (long)L * (2 * HID) * HID;
        const float* nb = n_b + (long)L * HID;
        const float* Ws = ew;
        const float* Wd = ew + (long)HID * HID;
        const float* We = ew + (long)2 * HID * HID;

        run_gemm(cur, Ws, HID, nullptr, nullptr, 0, nullptr, nullptr, 0, Xs, NN, HID, s);
        run_gemm(cur, Wd, HID, nullptr, nullptr, 0, nullptr, nullptr, 0, Xd, NN, HID, s);
        zero_kernel<<<(feat4 + zthr - 1) / zthr, zthr, 0, s>>>(agg, feat4);
        edge_kernel<<<NE / EPB, 256, 0, s>>>(Xs, Xd, eattr, We, eb, src, dst, agg, NE);
        run_gemm(cur, nw, HID, agg, nw + (long)HID * HID, HID, deg, nb, 1, nxt, NN, HID, s);

        float* t = cur; cur = nxt; nxt = t;
    }

    // ---------- head ----------
    // t = relu(cur @ h1_w + h1_b) -> nxt ; out = t @ h2_w + h2_b
    run_gemm(cur, h1_w, HID, nullptr, nullptr, 0, nullptr, h1_b, 1, nxt, NN, HID, s);
    head_out_kernel<<<(NN * 32 + 255) / 256, 256, 0, s>>>(nxt, h2_w, h2_b, (float*)d_out, NN);
}